// round 4
// baseline (speedup 1.0000x reference)
#include <cuda_runtime.h>

#define N_SPARSE 16
#define N_VARLEN 4
#define SEQ_L 50
#define VOCAB 1000000
#define EPSV 1e-8f
#define ROW_LEN (N_SPARSE + N_VARLEN * SEQ_L)   // 216
#define OUT_LEN (N_SPARSE + N_VARLEN)           // 20
#define ROWS_PER_WARP 2
#define WARPS_PER_BLOCK 8
#define THREADS (WARPS_PER_BLOCK * 32)          // 256
#define TAIL (SEQ_L - 32)                        // 18

__device__ __forceinline__ float warp_sum(float v) {
    #pragma unroll
    for (int o = 16; o; o >>= 1)
        v += __shfl_xor_sync(0xffffffffu, v, o);
    return v;
}

__global__ __launch_bounds__(THREADS) void emb_pool_kernel(
    const int* __restrict__ X,
    const float* __restrict__ sparse_tables,
    const float* __restrict__ varlen_tables,
    float* __restrict__ out)
{
    const int w    = threadIdx.x >> 5;
    const int lane = threadIdx.x & 31;
    const int row0 = (blockIdx.x * WARPS_PER_BLOCK + w) * ROWS_PER_WARP;

    const int* __restrict__ xr[ROWS_PER_WARP];
    xr[0] = X + (size_t)row0 * ROW_LEN;
    xr[1] = xr[0] + ROW_LEN;

    const bool tail_on = (lane < TAIL);

    // ================= Phase 1: all id loads (coalesced, independent) ======
    int sid[ROWS_PER_WARP];
    int ida[ROWS_PER_WARP][N_VARLEN];
    int idb[ROWS_PER_WARP][N_VARLEN];

    #pragma unroll
    for (int r = 0; r < ROWS_PER_WARP; r++) {
        sid[r] = (lane < N_SPARSE) ? __ldcg(xr[r] + lane) : 0;
        #pragma unroll
        for (int v = 0; v < N_VARLEN; v++) {
            const int* ids = xr[r] + N_SPARSE + v * SEQ_L;
            ida[r][v] = __ldcg(ids + lane);
            idb[r][v] = tail_on ? __ldcg(ids + 32 + lane) : 0;
        }
    }

    // ================= Phase 2: all gathers (independent, deep MLP) ========
    float sval[ROWS_PER_WARP];
    float ga[ROWS_PER_WARP][N_VARLEN];
    float gb[ROWS_PER_WARP][N_VARLEN];

    #pragma unroll
    for (int r = 0; r < ROWS_PER_WARP; r++) {
        sval[r] = (lane < N_SPARSE)
                ? __ldcg(sparse_tables + (size_t)lane * VOCAB + sid[r]) : 0.f;
        #pragma unroll
        for (int v = 0; v < N_VARLEN; v++) {
            ga[r][v] = (ida[r][v] != 0)
                     ? __ldcg(varlen_tables + (size_t)v * VOCAB + ida[r][v]) : 0.f;
            gb[r][v] = (idb[r][v] != 0)
                     ? __ldcg(varlen_tables + (size_t)v * VOCAB + idb[r][v]) : 0.f;
        }
    }

    // ================= Phase 3: counts (ballot) + sum reductions ===========
    int   cnt[ROWS_PER_WARP][N_VARLEN];
    float s  [ROWS_PER_WARP][N_VARLEN];

    #pragma unroll
    for (int r = 0; r < ROWS_PER_WARP; r++) {
        #pragma unroll
        for (int v = 0; v < N_VARLEN; v++) {
            unsigned b0 = __ballot_sync(0xffffffffu, ida[r][v] != 0);
            unsigned b1 = __ballot_sync(0xffffffffu, idb[r][v] != 0);
            cnt[r][v] = __popc(b0) + __popc(b1);
            s[r][v]   = warp_sum(ga[r][v] + gb[r][v]);
        }
    }

    // ================= Phase 4: coalesced stores (lanes 0..19) =============
    #pragma unroll
    for (int r = 0; r < ROWS_PER_WARP; r++) {
        float val;
        if (lane < N_SPARSE) {
            val = sval[r];
        } else {
            float sv, cv;
            if      (lane == 16) { sv = s[r][0]; cv = (float)cnt[r][0]; }
            else if (lane == 17) { sv = s[r][1]; cv = (float)cnt[r][1]; }
            else if (lane == 18) { sv = s[r][2]; cv = (float)cnt[r][2]; }
            else                 { sv = s[r][3]; cv = (float)cnt[r][3]; }
            val = sv / (cv + EPSV);
        }
        if (lane < OUT_LEN)
            out[(size_t)(row0 + r) * OUT_LEN + lane] = val;
    }
}

extern "C" void kernel_launch(void* const* d_in, const int* in_sizes, int n_in,
                              void* d_out, int out_size)
{
    const int*   X  = (const int*)d_in[0];
    const float* st = (const float*)d_in[1];
    const float* vt = (const float*)d_in[2];
    float* out = (float*)d_out;

    const int B = in_sizes[0] / ROW_LEN;                       // 16384
    const int grid = B / (ROWS_PER_WARP * WARPS_PER_BLOCK);    // 1024

    emb_pool_kernel<<<grid, THREADS>>>(X, st, vt, out);
}

// round 6
// speedup vs baseline: 1.1049x; 1.1049x over previous
#include <cuda_runtime.h>

#define N_SPARSE 16
#define N_VARLEN 4
#define SEQ_L 50
#define VOCAB 1000000
#define EPSV 1e-8f
#define ROW_LEN (N_SPARSE + N_VARLEN * SEQ_L)   // 216
#define OUT_LEN (N_SPARSE + N_VARLEN)           // 20
#define ROWS_PER_BLOCK 8
#define THREADS (ROWS_PER_BLOCK * 32)           // 256
#define TAIL (SEQ_L - 32)                        // 18

// L2 evict-last policy for table gathers (tables: 80MB, L2: 126MB).
__device__ __forceinline__ unsigned long long make_persist_policy() {
    unsigned long long pol;
    asm("createpolicy.fractional.L2::evict_last.b64 %0, 1.0;" : "=l"(pol));
    return pol;
}

__device__ __forceinline__ float ldg_persist(const float* p, unsigned long long pol) {
    float v;
    asm("ld.global.nc.L2::cache_hint.f32 %0, [%1], %2;"
        : "=f"(v) : "l"(p), "l"(pol));
    return v;
}

__global__ __launch_bounds__(THREADS) void emb_pool_kernel(
    const int* __restrict__ X,
    const float* __restrict__ sparse_tables,
    const float* __restrict__ varlen_tables,
    float* __restrict__ out)
{
    __shared__ int sx[ROWS_PER_BLOCK][ROW_LEN];

    const int tid  = threadIdx.x;
    const int base = blockIdx.x * ROWS_PER_BLOCK;
    const unsigned long long pol = make_persist_policy();

    // Coalesced, vectorized, streaming stage of 8 rows of X into smem.
    // 8*216 = 1728 ints = 432 int4; block offset (6912B) is 16B-aligned.
    {
        const int4* Xb4 = (const int4*)(X + (size_t)base * ROW_LEN);
        int4* sx4 = (int4*)&sx[0][0];
        #pragma unroll
        for (int i = tid; i < (ROWS_PER_BLOCK * ROW_LEN) / 4; i += THREADS)
            sx4[i] = __ldcs(Xb4 + i);
    }
    __syncthreads();

    const int w    = tid >> 5;
    const int lane = tid & 31;
    const int row  = base + w;
    float* orow = out + (size_t)row * OUT_LEN;

    // ---- Sparse features: lanes 0..15 each do one gather ----
    float sparse_val = 0.f;
    if (lane < N_SPARSE) {
        int id = sx[w][lane];
        sparse_val = ldg_persist(sparse_tables + (size_t)lane * VOCAB + id, pol);
    }

    // ---- Varlen features: gathers + ballot counts ----
    float s[N_VARLEN];
    int   cnt[N_VARLEN];

    #pragma unroll
    for (int v = 0; v < N_VARLEN; v++) {
        const int* ids = &sx[w][N_SPARSE + v * SEQ_L];
        int id0 = ids[lane];
        bool p0 = (id0 != 0);
        float sv = 0.f;
        if (p0) sv = ldg_persist(varlen_tables + (size_t)v * VOCAB + id0, pol);

        bool active1 = (lane < TAIL);
        int id1 = active1 ? ids[32 + lane] : 0;
        bool p1 = (id1 != 0);
        if (p1) sv += ldg_persist(varlen_tables + (size_t)v * VOCAB + id1, pol);

        unsigned b0 = __ballot_sync(0xffffffffu, p0);
        unsigned b1 = __ballot_sync(0xffffffffu, p1);
        cnt[v] = __popc(b0) + __popc(b1);
        s[v] = sv;
    }

    // Sum reductions (independent trees, pipelined)
    #pragma unroll
    for (int v = 0; v < N_VARLEN; v++) {
        float sv = s[v];
        #pragma unroll
        for (int o = 16; o; o >>= 1)
            sv += __shfl_xor_sync(0xffffffffu, sv, o);
        s[v] = sv;
    }

    // ---- Single coalesced streaming store: lanes 0..19 ----
    float val;
    if (lane < N_SPARSE) {
        val = sparse_val;
    } else {
        float sv, cv;
        if      (lane == 16) { sv = s[0]; cv = (float)cnt[0]; }
        else if (lane == 17) { sv = s[1]; cv = (float)cnt[1]; }
        else if (lane == 18) { sv = s[2]; cv = (float)cnt[2]; }
        else                 { sv = s[3]; cv = (float)cnt[3]; }
        val = sv / (cv + EPSV);
    }
    if (lane < OUT_LEN)
        __stcs(orow + lane, val);
}

extern "C" void kernel_launch(void* const* d_in, const int* in_sizes, int n_in,
                              void* d_out, int out_size)
{
    const int*   X  = (const int*)d_in[0];
    const float* st = (const float*)d_in[1];
    const float* vt = (const float*)d_in[2];
    float* out = (float*)d_out;

    const int B = in_sizes[0] / ROW_LEN;     // 16384
    const int grid = B / ROWS_PER_BLOCK;     // 2048

    emb_pool_kernel<<<grid, THREADS>>>(X, st, vt, out);
}